// round 3
// baseline (speedup 1.0000x reference)
#include <cuda_runtime.h>

// Problem constants
static constexpr int B_DIM = 256;
static constexpr int N_DIM = 65536;
static constexpr int BN    = B_DIM * N_DIM;          // 16,777,216
static constexpr int BN4   = BN / 4;                 // 4,194,304 float4 per tensor
static constexpr int N4    = N_DIM / 4;              // 16,384 float4 in row 0

static constexpr int THREADS = 256;
static constexpr int ILP     = 4;
static constexpr int CHUNK   = THREADS * ILP;        // 1024 float4 per block
static constexpr int BLOCKS  = BN4 / CHUNK;          // 4096
static constexpr int ROW0_BLOCKS = N4 / CHUNK;       // 16 (exact, whole blocks)

// LIF-AdEx parameters (defaults from reference)
#define TAU_SYN_INV   0.5f
#define TAU_MEM_INV   0.5f
#define V_TH          1.0f
#define V_PEAK        30.0f
#define INHIBITION    (-5.0f)

// Elementwise step — single definition, used both for the winner scan and the
// output pass, so row-0 spike decisions are bit-identical.
__device__ __forceinline__ void lif_step(float x, float v, float i, float w,
                                         float& z, float& v_out, float& i_new,
                                         float& w_new, float& v_before) {
    i_new = fmaf(TAU_SYN_INV, x - i, i);                 // i + 0.5*(x - i)
    float e = __expf(v - V_TH);                          // delta_t*exp((v-v_th)/delta_t)
    float s = e + i_new - w - v;                         // -(v-v_rest) + e + i_new - w
    float vn = fmaf(TAU_MEM_INV, s, v);                  // v + 0.5*s
    w_new = 0.5f * w;                                    // a_param = 0
    v_before = vn;
    bool spike = (vn >= V_PEAK);
    z = spike ? 1.0f : 0.0f;
    v_out = spike ? 0.0f : vn;                           // v_reset=0, b_param=0
}

__device__ __forceinline__ unsigned long long
umax64(unsigned long long a, unsigned long long b) { return a > b ? a : b; }

// Winner key: upper 32 bits = float bits of v_before (v_before >= 30 > 0 when
// spiked, so raw positive-float bits are order-preserving); lower 32 bits =
// 0xFFFFFFFF - col so max picks the LOWEST column on value ties (jnp.argmax).
// key == 0 <=> no spike in row 0.
__device__ __forceinline__ unsigned long long
winner_key(float vb, unsigned col) {
    return ((unsigned long long)__float_as_uint(vb) << 32) |
           (unsigned long long)(0xFFFFFFFFu - col);
}

// Single fused kernel. The 16 row-0 blocks each redundantly scan all of row 0
// (1 MB, mostly L2-resident) to compute the SAME winner key deterministically —
// no second kernel, no atomics, no device globals.
__global__ void __launch_bounds__(THREADS)
k_fused(const float4* __restrict__ x,
        const float4* __restrict__ v,
        const float4* __restrict__ i,
        const float4* __restrict__ w,
        float4* __restrict__ out) {
    const int  base = blockIdx.x * CHUNK + threadIdx.x;
    const bool row0 = (blockIdx.x < ROW0_BLOCKS);

    __shared__ unsigned long long s_key;

    if (row0) {
        // Full row-0 winner scan: 64 float4 per thread.
        unsigned long long best = 0ULL;
        for (int t = threadIdx.x; t < N4; t += THREADS) {
            float4 xf = x[t], vf = v[t], if4 = i[t], wf = w[t];
            float xs[4] = {xf.x, xf.y, xf.z, xf.w};
            float vs[4] = {vf.x, vf.y, vf.z, vf.w};
            float is[4] = {if4.x, if4.y, if4.z, if4.w};
            float ws[4] = {wf.x, wf.y, wf.z, wf.w};
#pragma unroll
            for (int k = 0; k < 4; k++) {
                float z, vo, in, wn, vb;
                lif_step(xs[k], vs[k], is[k], ws[k], z, vo, in, wn, vb);
                if (vb >= V_PEAK)
                    best = umax64(best, winner_key(vb, (unsigned)(t * 4 + k)));
            }
        }
        // warp reduce
#pragma unroll
        for (int o = 16; o > 0; o >>= 1)
            best = umax64(best, __shfl_down_sync(0xFFFFFFFFu, best, o));
        // cross-warp reduce (8 warps)
        __shared__ unsigned long long s_warp[THREADS / 32];
        int wid = threadIdx.x >> 5, lid = threadIdx.x & 31;
        if (lid == 0) s_warp[wid] = best;
        __syncthreads();
        if (threadIdx.x < 32) {
            unsigned long long kk =
                (threadIdx.x < THREADS / 32) ? s_warp[threadIdx.x] : 0ULL;
#pragma unroll
            for (int o = 4; o > 0; o >>= 1)
                kk = umax64(kk, __shfl_down_sync(0xFFFFFFFFu, kk, o));
            if (threadIdx.x == 0) s_key = kk;
        }
        __syncthreads();
    }

    // ---- streaming pass: front-batch ALL loads for max MLP ----
    float4 xf[ILP], vf[ILP], if4[ILP], wf[ILP];
#pragma unroll
    for (int c = 0; c < ILP; c++) {
        const int t = base + c * THREADS;
        xf[c]  = __ldcs(&x[t]);
        vf[c]  = __ldcs(&v[t]);
        if4[c] = __ldcs(&i[t]);
        wf[c]  = __ldcs(&w[t]);
    }

    unsigned long long key = 0ULL;
    unsigned winner = 0xFFFFFFFFu;
    if (row0) {
        key = s_key;
        winner = 0xFFFFFFFFu - (unsigned)(key & 0xFFFFFFFFull);
    }

#pragma unroll
    for (int c = 0; c < ILP; c++) {
        const int t = base + c * THREADS;
        float xs[4] = {xf[c].x, xf[c].y, xf[c].z, xf[c].w};
        float vs[4] = {vf[c].x, vf[c].y, vf[c].z, vf[c].w};
        float is[4] = {if4[c].x, if4[c].y, if4[c].z, if4[c].w};
        float ws[4] = {wf[c].x, wf[c].y, wf[c].z, wf[c].w};

        float zo[4], vo[4], io[4], wo[4];
#pragma unroll
        for (int k = 0; k < 4; k++) {
            float vb;
            lif_step(xs[k], vs[k], is[k], ws[k], zo[k], vo[k], io[k], wo[k], vb);
        }

        if (row0 && key != 0ULL) {                       // any_spike0
            int col = t * 4;
#pragma unroll
            for (int k = 0; k < 4; k++) {
                if ((unsigned)(col + k) != winner) {     // inhibit all but winner
                    vo[k] = INHIBITION;
                    wo[k] = 0.0f;
                }
            }
        }

        __stcs(&out[t],           make_float4(zo[0], zo[1], zo[2], zo[3]));
        __stcs(&out[BN4 + t],     make_float4(vo[0], vo[1], vo[2], vo[3]));
        __stcs(&out[2 * BN4 + t], make_float4(io[0], io[1], io[2], io[3]));
        __stcs(&out[3 * BN4 + t], make_float4(wo[0], wo[1], wo[2], wo[3]));
    }
}

extern "C" void kernel_launch(void* const* d_in, const int* in_sizes, int n_in,
                              void* d_out, int out_size) {
    const float4* x = (const float4*)d_in[0];
    const float4* v = (const float4*)d_in[1];
    const float4* i = (const float4*)d_in[2];
    const float4* w = (const float4*)d_in[3];
    float4* out = (float4*)d_out;

    k_fused<<<BLOCKS, THREADS>>>(x, v, i, w, out);
}